// round 1
// baseline (speedup 1.0000x reference)
#include <cuda_runtime.h>

#define BB 256
#define TT 2048

// layer-0 output scratch: h1[t][b][64]  (forward dir -> [0:32), backward -> [32:64))
__device__ float g_h1[(size_t)TT * BB * 64];

__device__ __forceinline__ float sigf(float x) {
    return __fdividef(1.0f, 1.0f + __expf(-x));
}
__device__ __forceinline__ float tanh_fast(float x) {
    // tanh(x) = 1 - 2/(exp(2x)+1); saturates correctly at +-1 via inf/0
    return 1.0f - __fdividef(2.0f, __expf(2.0f * x) + 1.0f);
}

// One bidirectional-LSTM direction per blockIdx.y, NB batch elements per block.
// 128 threads: thread t owns gate row t (PyTorch order: i[0:32) f[32:64) g[64:96) o[96:128)).
// Weights live in registers; h/c recurrence + gate exchange through shared memory.
template<int F, int NB, bool L0>
__global__ __launch_bounds__(128)
void lstm_layer(const float* __restrict__ oseq,   // [B,T,16]  (L0 only)
                const float* __restrict__ iseq,   // [B,T,16]  (L0 only)
                const float* __restrict__ Wih,    // [2,128,F]
                const float* __restrict__ Whh,    // [2,128,32]
                const float* __restrict__ bih,    // [2,128]
                const float* __restrict__ bhh,    // [2,128]
                float* __restrict__ out)          // L1: d_out [B,T,64]
{
    const int dir = blockIdx.y;
    const int b0  = blockIdx.x * NB;
    const int tid = threadIdx.x;

    // per-thread weight rows in registers
    float wih[F];
    {
        const float* p = Wih + (size_t)(dir * 128 + tid) * F;
        #pragma unroll
        for (int k = 0; k < F; k++) wih[k] = p[k];
    }
    float whh[32];
    {
        const float* p = Whh + (size_t)(dir * 128 + tid) * 32;
        #pragma unroll
        for (int k = 0; k < 32; k++) whh[k] = p[k];
    }
    const float bias = bih[dir * 128 + tid] + bhh[dir * 128 + tid];

    __shared__ __align__(16) float x_sh[2][NB][F];
    __shared__ __align__(16) float h_sh[NB][32];
    __shared__ __align__(16) float g_sh[NB][128];

    if (tid < NB * 32) h_sh[tid >> 5][tid & 31] = 0.0f;

    const int pb = tid >> 5;      // phase-2 batch index (tid < NB*32)
    const int pj = tid & 31;      // phase-2 hidden index
    float c = 0.0f;

    // one x element per thread (NB*F <= 128)
    const int  e     = tid;
    const int  eb    = e / F;
    const int  ek    = e % F;
    const bool eload = (e < NB * F);

    auto ldx = [&](int t) -> float {
        if (L0) {
            // io = concat(output_sequence[:,t], input_sequence[:,T-1-t])
            if (ek < 16) return oseq[((size_t)(b0 + eb) * TT + t) * 16 + ek];
            else         return iseq[((size_t)(b0 + eb) * TT + (TT - 1 - t)) * 16 + (ek - 16)];
        } else {
            return g_h1[((size_t)t * BB + (b0 + eb)) * 64 + ek];
        }
    };

    // prologue: stage x for step 0
    {
        const int t0 = dir ? (TT - 1) : 0;
        if (eload) x_sh[0][eb][ek] = ldx(t0);
    }
    __syncthreads();

    for (int s = 0; s < TT; s++) {
        const int cur = s & 1;

        // prefetch next step's x (latency hidden behind gate FMAs)
        float pf = 0.0f;
        {
            const int sn = (s + 1 < TT) ? (s + 1) : s;
            const int tn = dir ? (TT - 1 - sn) : sn;
            if (eload) pf = ldx(tn);
        }

        // phase 1: gate pre-activations for NB batch elements
        float acc[NB];
        #pragma unroll
        for (int b = 0; b < NB; b++) acc[b] = bias;

        #pragma unroll
        for (int k4 = 0; k4 < F / 4; k4++) {
            #pragma unroll
            for (int b = 0; b < NB; b++) {
                const float4 v = *(const float4*)&x_sh[cur][b][k4 * 4];
                acc[b] = fmaf(wih[k4 * 4 + 0], v.x, acc[b]);
                acc[b] = fmaf(wih[k4 * 4 + 1], v.y, acc[b]);
                acc[b] = fmaf(wih[k4 * 4 + 2], v.z, acc[b]);
                acc[b] = fmaf(wih[k4 * 4 + 3], v.w, acc[b]);
            }
        }
        #pragma unroll
        for (int k4 = 0; k4 < 8; k4++) {
            #pragma unroll
            for (int b = 0; b < NB; b++) {
                const float4 v = *(const float4*)&h_sh[b][k4 * 4];
                acc[b] = fmaf(whh[k4 * 4 + 0], v.x, acc[b]);
                acc[b] = fmaf(whh[k4 * 4 + 1], v.y, acc[b]);
                acc[b] = fmaf(whh[k4 * 4 + 2], v.z, acc[b]);
                acc[b] = fmaf(whh[k4 * 4 + 3], v.w, acc[b]);
            }
        }
        #pragma unroll
        for (int b = 0; b < NB; b++) g_sh[b][tid] = acc[b];

        // commit prefetch into the other x buffer
        if (eload) x_sh[cur ^ 1][eb][ek] = pf;
        __syncthreads();

        // phase 2: LSTM cell update (NB*32 threads)
        if (tid < NB * 32) {
            const float gi = g_sh[pb][pj];
            const float gf = g_sh[pb][32 + pj];
            const float gg = g_sh[pb][64 + pj];
            const float go = g_sh[pb][96 + pj];
            c = sigf(gf) * c + sigf(gi) * tanh_fast(gg);
            const float h = sigf(go) * tanh_fast(c);
            h_sh[pb][pj] = h;

            const int t = dir ? (TT - 1 - s) : s;
            if (L0) g_h1[((size_t)t * BB + (b0 + pb)) * 64 + dir * 32 + pj] = h;
            else    out[((size_t)(b0 + pb) * TT + t) * 64 + dir * 32 + pj]  = h;
        }
        __syncthreads();
    }
}

extern "C" void kernel_launch(void* const* d_in, const int* in_sizes, int n_in,
                              void* d_out, int out_size) {
    (void)in_sizes; (void)n_in; (void)out_size;
    const float* oseq  = (const float*)d_in[0];  // output_sequence [256,2048,16]
    const float* iseq  = (const float*)d_in[1];  // input_sequence  [256,2048,16]
    const float* Wih0  = (const float*)d_in[2];  // [2,128,32]
    const float* Whh0  = (const float*)d_in[3];  // [2,128,32]
    const float* bih0  = (const float*)d_in[4];  // [2,128]
    const float* bhh0  = (const float*)d_in[5];
    const float* Wih1  = (const float*)d_in[6];  // [2,128,64]
    const float* Whh1  = (const float*)d_in[7];  // [2,128,32]
    const float* bih1  = (const float*)d_in[8];
    const float* bhh1  = (const float*)d_in[9];
    float* out = (float*)d_out;                  // [256,2048,64]

    constexpr int NB = 2;
    dim3 grid(BB / NB, 2);

    lstm_layer<32, NB, true ><<<grid, 128>>>(oseq, iseq, Wih0, Whh0, bih0, bhh0, nullptr);
    lstm_layer<64, NB, false><<<grid, 128>>>(nullptr, nullptr, Wih1, Whh1, bih1, bhh1, out);
}

// round 2
// speedup vs baseline: 1.2068x; 1.2068x over previous
#include <cuda_runtime.h>

typedef unsigned long long ull;

#define BB 256
#define TT 2048

// layer-0 output scratch: h1[t][b][64]  (fwd -> [0:32), bwd -> [32:64))
__device__ float g_h1[(size_t)TT * BB * 64];

__device__ __forceinline__ float sigf(float x) {
    return __fdividef(1.0f, 1.0f + __expf(-x));
}
__device__ __forceinline__ float tanh_fast(float x) {
    return 1.0f - __fdividef(2.0f, __expf(2.0f * x) + 1.0f);
}

__device__ __forceinline__ ull pack2(float lo, float hi) {
    ull r;
    asm("mov.b64 %0, {%1, %2};" : "=l"(r) : "f"(lo), "f"(hi));
    return r;
}
__device__ __forceinline__ void unpack2(ull v, float& lo, float& hi) {
    asm("mov.b64 {%0, %1}, %2;" : "=f"(lo), "=f"(hi) : "l"(v));
}
__device__ __forceinline__ ull ffma2(ull a, ull b, ull c) {
    ull d;
    asm("fma.rn.f32x2 %0, %1, %2, %3;" : "=l"(d) : "l"(a), "l"(b), "l"(c));
    return d;
}

// 256 threads = 2 gate-groups of 128. Group g handles batches {2g, 2g+1}.
// Thread (group, tig): gate row tig (PyTorch order i,f,g,o x 32).
// K-reduction packed into f32x2 (even/odd k lanes).
template<int F, bool L0>
__global__ __launch_bounds__(256)
void lstm_layer(const float* __restrict__ oseq,   // [B,T,16]  (L0 only)
                const float* __restrict__ iseq,   // [B,T,16]  (L0 only)
                const float* __restrict__ Wih,    // [2,128,F]
                const float* __restrict__ Whh,    // [2,128,32]
                const float* __restrict__ bih,    // [2,128]
                const float* __restrict__ bhh,    // [2,128]
                float* __restrict__ out)          // L1: d_out [B,T,64]
{
    constexpr int NBT = 4;                 // batches per block
    const int dir = blockIdx.y;
    const int b0  = blockIdx.x * NBT;
    const int tid = threadIdx.x;
    const int grp = tid >> 7;              // 0 or 1
    const int tig = tid & 127;             // gate row within group

    // packed weight rows in registers: {w[2k], w[2k+1]}
    ull wih2[F / 2];
    {
        const float* p = Wih + (size_t)(dir * 128 + tig) * F;
        #pragma unroll
        for (int k = 0; k < F / 2; k++) wih2[k] = pack2(p[2 * k], p[2 * k + 1]);
    }
    ull whh2[16];
    {
        const float* p = Whh + (size_t)(dir * 128 + tig) * 32;
        #pragma unroll
        for (int k = 0; k < 16; k++) whh2[k] = pack2(p[2 * k], p[2 * k + 1]);
    }
    const float bias = bih[dir * 128 + tig] + bhh[dir * 128 + tig];

    __shared__ __align__(16) float x_sh[2][NBT][F];
    __shared__ __align__(16) float h_sh[NBT][32];
    __shared__ __align__(16) float g_sh[NBT][128];

    // phase-2 mapping: group 0 -> warps 0,1 of group; group 1 -> warps 2,3
    // (lands the MUFU-heavy cell update on 4 distinct SMSPs)
    const int w2   = (tig >> 5) ^ (grp << 1);
    const bool p2  = (w2 < 2);
    const int pb   = grp * 2 + (w2 & 1);   // batch (valid when p2)
    const int pj   = tig & 31;             // hidden index
    float c = 0.0f;

    if (p2) h_sh[pb][pj] = 0.0f;

    // x staging: one element per thread (NBT*F <= 256)
    const int  e     = tid;
    const int  eb    = e / F;
    const int  ek    = e % F;
    const bool eload = (e < NBT * F);

    auto ldx = [&](int t) -> float {
        if (L0) {
            if (ek < 16) return oseq[((size_t)(b0 + eb) * TT + t) * 16 + ek];
            else         return iseq[((size_t)(b0 + eb) * TT + (TT - 1 - t)) * 16 + (ek - 16)];
        } else {
            return g_h1[((size_t)t * BB + (b0 + eb)) * 64 + ek];
        }
    };

    {
        const int t0 = dir ? (TT - 1) : 0;
        if (eload) x_sh[0][eb][ek] = ldx(t0);
    }
    __syncthreads();

    const int ba = grp * 2;       // first batch of this group
    const int bb2 = grp * 2 + 1;  // second batch

    for (int s = 0; s < TT; s++) {
        const int cur = s & 1;

        // prefetch next step's x
        float pf = 0.0f;
        {
            const int sn = (s + 1 < TT) ? (s + 1) : s;
            const int tn = dir ? (TT - 1 - sn) : sn;
            if (eload) pf = ldx(tn);
        }

        // phase 1: packed gate pre-activations, 2 batches per group
        ull acc0 = pack2(0.0f, 0.0f);
        ull acc1 = pack2(0.0f, 0.0f);
        {
            const ull* xa = (const ull*)x_sh[cur][ba];
            const ull* xb = (const ull*)x_sh[cur][bb2];
            #pragma unroll
            for (int k = 0; k < F / 2; k++) {
                acc0 = ffma2(wih2[k], xa[k], acc0);
                acc1 = ffma2(wih2[k], xb[k], acc1);
            }
            const ull* ha = (const ull*)h_sh[ba];
            const ull* hb = (const ull*)h_sh[bb2];
            #pragma unroll
            for (int k = 0; k < 16; k++) {
                acc0 = ffma2(whh2[k], ha[k], acc0);
                acc1 = ffma2(whh2[k], hb[k], acc1);
            }
        }
        {
            float lo, hi;
            unpack2(acc0, lo, hi);
            g_sh[ba][tig] = lo + hi + bias;
            unpack2(acc1, lo, hi);
            g_sh[bb2][tig] = lo + hi + bias;
        }

        // commit prefetch into the other buffer
        if (eload) x_sh[cur ^ 1][eb][ek] = pf;
        __syncthreads();

        // phase 2: cell update (4 warps, one per SMSP)
        if (p2) {
            const float gi = g_sh[pb][pj];
            const float gf = g_sh[pb][32 + pj];
            const float gg = g_sh[pb][64 + pj];
            const float go = g_sh[pb][96 + pj];
            c = sigf(gf) * c + sigf(gi) * tanh_fast(gg);
            const float h = sigf(go) * tanh_fast(c);
            h_sh[pb][pj] = h;

            const int t = dir ? (TT - 1 - s) : s;
            if (L0) g_h1[((size_t)t * BB + (b0 + pb)) * 64 + dir * 32 + pj] = h;
            else    out[((size_t)(b0 + pb) * TT + t) * 64 + dir * 32 + pj]  = h;
        }
        __syncthreads();
    }
}

extern "C" void kernel_launch(void* const* d_in, const int* in_sizes, int n_in,
                              void* d_out, int out_size) {
    (void)in_sizes; (void)n_in; (void)out_size;
    const float* oseq  = (const float*)d_in[0];
    const float* iseq  = (const float*)d_in[1];
    const float* Wih0  = (const float*)d_in[2];
    const float* Whh0  = (const float*)d_in[3];
    const float* bih0  = (const float*)d_in[4];
    const float* bhh0  = (const float*)d_in[5];
    const float* Wih1  = (const float*)d_in[6];
    const float* Whh1  = (const float*)d_in[7];
    const float* bih1  = (const float*)d_in[8];
    const float* bhh1  = (const float*)d_in[9];
    float* out = (float*)d_out;

    dim3 grid(BB / 4, 2);   // 128 blocks, one per SM

    lstm_layer<32, true ><<<grid, 256>>>(oseq, iseq, Wih0, Whh0, bih0, bhh0, nullptr);
    lstm_layer<64, false><<<grid, 256>>>(nullptr, nullptr, Wih1, Whh1, bih1, bhh1, out);
}